// round 1
// baseline (speedup 1.0000x reference)
#include <cuda_runtime.h>

// Problem constants
#define NB 16
#define NH 32
#define NG 8
#define ND 4096
#define DK 128
#define DV 128
#define NM 8192
#define NM1 8193

// Output layout: y [16,4096] | Kc [16,8,8193,128] | Vc [16,8,8193,128]
static const long long KC_OFF = 65536LL;
static const long long VC_OFF = 65536LL + 16LL * 8 * 8193 * 128; // 134299648

// Scratch (device globals — no allocations allowed)
__device__ float g_proj_part[8 * 16 * 48 * 128];   // split-D partials for q/k_new/v_new
__device__ float g_proj[16 * 48 * 128];            // n<32: q[h], 32..39: k_new[g], 40..47: v_new[g]
__device__ float g_logits[16 * 32 * 8193];         // logits, then softmax weights (in place)
__device__ float g_opart[16 * 8 * 64 * 512];       // per-(b,g,chunk) partial o (4 heads x 128 v)
__device__ float g_o[16 * 32 * 128];               // attention output per head
__device__ float g_ypart[8 * 16 * 4096];           // split-hv partials of y

// ---------------------------------------------------------------------------
// K1: projections, split over D. grid (48, 8), block 128 (k-index).
// n<32 -> q head n; 32..39 -> k_new group n-32; 40..47 -> v_new group n-40.
// ---------------------------------------------------------------------------
__global__ void k_proj_partial(const float* __restrict__ x,
                               const float* __restrict__ Wq,
                               const float* __restrict__ Wk,
                               const float* __restrict__ Wv) {
    int n = blockIdx.x;
    int c = blockIdx.y;
    int tid = threadIdx.x;
    int d0 = c * 512;
    const float* W = (n < 32) ? (Wq + (size_t)n * ND * DK)
                   : (n < 40) ? (Wk + (size_t)(n - 32) * ND * DK)
                              : (Wv + (size_t)(n - 40) * ND * DK);
    __shared__ float xs[16 * 512];
    for (int idx = tid; idx < 16 * 512; idx += 128) {
        int b = idx >> 9, d = idx & 511;
        xs[idx] = x[b * ND + d0 + d];
    }
    __syncthreads();
    float acc[16];
#pragma unroll
    for (int b = 0; b < 16; b++) acc[b] = 0.f;
    for (int d = 0; d < 512; d += 4) {
        float w0 = W[(size_t)(d0 + d + 0) * DK + tid];
        float w1 = W[(size_t)(d0 + d + 1) * DK + tid];
        float w2 = W[(size_t)(d0 + d + 2) * DK + tid];
        float w3 = W[(size_t)(d0 + d + 3) * DK + tid];
#pragma unroll
        for (int b = 0; b < 16; b++) {
            float4 xv = *(const float4*)&xs[b * 512 + d];
            acc[b] += xv.x * w0 + xv.y * w1 + xv.z * w2 + xv.w * w3;
        }
    }
#pragma unroll
    for (int b = 0; b < 16; b++)
        g_proj_part[((c * 16 + b) * 48 + n) * 128 + tid] = acc[b];
}

// K2: reduce split-D partials; also append new-token rows into Kc / Vc (m = 8192)
__global__ void k_proj_reduce(float* __restrict__ out) {
    int bn = blockIdx.x;
    int b = bn / 48, n = bn % 48;
    int tid = threadIdx.x;
    float s = 0.f;
#pragma unroll
    for (int c = 0; c < 8; c++)
        s += g_proj_part[((c * 16 + b) * 48 + n) * 128 + tid];
    g_proj[(b * 48 + n) * 128 + tid] = s;
    if (n >= 32 && n < 40) {
        out[KC_OFF + ((long long)(b * 8 + n - 32) * NM1 + NM) * 128 + tid] = s;
    } else if (n >= 40) {
        out[VC_OFF + ((long long)(b * 8 + n - 40) * NM1 + NM) * 128 + tid] = s;
    }
}

// ---------------------------------------------------------------------------
// K3: fused prev_K copy -> Kc + logits for 4 heads per group.
// grid = B*G*64 (128-row chunks), block 256 (8 warps, one row per warp-iter).
// ---------------------------------------------------------------------------
__global__ void k_logits_copyK(const float* __restrict__ prevK,
                               float* __restrict__ out) {
    int bg = blockIdx.x >> 6;
    int chunk = blockIdx.x & 63;
    int b = bg >> 3, g = bg & 7;
    int tid = threadIdx.x, warp = tid >> 5, lane = tid & 31;
    int m0 = chunk * 128;

    __shared__ float qs[512];   // q for heads ri*8+g, ri=0..3
    __shared__ float ls[512];   // staged logits (coalesced write-out)
    for (int idx = tid; idx < 512; idx += 256) {
        int ri = idx >> 7, k = idx & 127;
        qs[idx] = g_proj[(b * 48 + ri * 8 + g) * 128 + k];
    }
    __syncthreads();
    const float4* qs4 = (const float4*)qs;
    float4 q0 = qs4[lane], q1 = qs4[32 + lane], q2 = qs4[64 + lane], q3 = qs4[96 + lane];

    const float4* src = (const float4*)(prevK + ((size_t)bg * NM + m0) * 128);
    float4* dst = (float4*)(out + KC_OFF + ((long long)bg * NM1 + m0) * 128);

    for (int r = warp; r < 128; r += 8) {
        float4 kv = __ldcs(src + r * 32 + lane);
        __stcs(dst + r * 32 + lane, kv);
        float s0 = kv.x * q0.x + kv.y * q0.y + kv.z * q0.z + kv.w * q0.w;
        float s1 = kv.x * q1.x + kv.y * q1.y + kv.z * q1.z + kv.w * q1.w;
        float s2 = kv.x * q2.x + kv.y * q2.y + kv.z * q2.z + kv.w * q2.w;
        float s3 = kv.x * q3.x + kv.y * q3.y + kv.z * q3.z + kv.w * q3.w;
#pragma unroll
        for (int off = 16; off > 0; off >>= 1) {
            s0 += __shfl_xor_sync(0xffffffffu, s0, off);
            s1 += __shfl_xor_sync(0xffffffffu, s1, off);
            s2 += __shfl_xor_sync(0xffffffffu, s2, off);
            s3 += __shfl_xor_sync(0xffffffffu, s3, off);
        }
        if (lane == 0) {
            ls[r] = s0; ls[128 + r] = s1; ls[256 + r] = s2; ls[384 + r] = s3;
        }
    }
    __syncthreads();
    for (int idx = tid; idx < 512; idx += 256) {
        int ri = idx >> 7, i = idx & 127;
        g_logits[(size_t)(b * 32 + ri * 8 + g) * NM1 + m0 + i] = ls[idx];
    }
}

// ---------------------------------------------------------------------------
// K4: softmax per (b,h) over 8193 logits; also computes the new-token logit
// q . k_new. Weights written back in place (g_logits).
// ---------------------------------------------------------------------------
__global__ void k_softmax() {
    int bh = blockIdx.x;
    int b = bh >> 5, h = bh & 31, g = h & 7;
    int tid = threadIdx.x; // 256

    __shared__ float buf[8192];
    __shared__ float red[256];

    // new-token logit
    float p = 0.f;
    if (tid < 128)
        p = g_proj[(b * 48 + h) * 128 + tid] * g_proj[(b * 48 + 32 + g) * 128 + tid];
    red[tid] = p;
    __syncthreads();
    for (int s = 128; s > 0; s >>= 1) {
        if (tid < s) red[tid] += red[tid + s];
        __syncthreads();
    }
    float newl = red[0];
    __syncthreads();

    size_t base = (size_t)bh * NM1;
    float mx = -3.4e38f;
    for (int i = tid; i < 8192; i += 256) {
        float l = g_logits[base + i];
        buf[i] = l;
        mx = fmaxf(mx, l);
    }
    red[tid] = mx;
    __syncthreads();
    for (int s = 128; s > 0; s >>= 1) {
        if (tid < s) red[tid] = fmaxf(red[tid], red[tid + s]);
        __syncthreads();
    }
    mx = fmaxf(red[0], newl);
    __syncthreads();

    float sm = 0.f;
    for (int i = tid; i < 8192; i += 256) {
        float e = __expf(buf[i] - mx);
        buf[i] = e;
        sm += e;
    }
    red[tid] = sm;
    __syncthreads();
    for (int s = 128; s > 0; s >>= 1) {
        if (tid < s) red[tid] += red[tid + s];
        __syncthreads();
    }
    float en = __expf(newl - mx);
    float inv = 1.f / (red[0] + en);
    for (int i = tid; i < 8192; i += 256)
        g_logits[base + i] = buf[i] * inv;
    if (tid == 0) g_logits[base + 8192] = en * inv;
}

// ---------------------------------------------------------------------------
// K5: fused prev_V copy -> Vc + weighted accumulation of o (4 heads/group).
// Same structure as K3; per-warp register accumulators, in-block reduce.
// ---------------------------------------------------------------------------
__global__ void k_attnV_copyV(const float* __restrict__ prevV,
                              float* __restrict__ out) {
    int bg = blockIdx.x >> 6;
    int chunk = blockIdx.x & 63;
    int b = bg >> 3, g = bg & 7;
    int tid = threadIdx.x, warp = tid >> 5, lane = tid & 31;
    int m0 = chunk * 128;

    __shared__ float ws[512];        // softmax weights for 4 heads x 128 rows
    __shared__ float accs[8 * 512];  // per-warp partials
    for (int idx = tid; idx < 512; idx += 256) {
        int ri = idx >> 7, i = idx & 127;
        ws[idx] = g_logits[(size_t)(b * 32 + ri * 8 + g) * NM1 + m0 + i];
    }
    __syncthreads();

    const float4* src = (const float4*)(prevV + ((size_t)bg * NM + m0) * 128);
    float4* dst = (float4*)(out + VC_OFF + ((long long)bg * NM1 + m0) * 128);

    float4 a0 = {0, 0, 0, 0}, a1 = a0, a2 = a0, a3 = a0;
    for (int r = warp; r < 128; r += 8) {
        float4 v = __ldcs(src + r * 32 + lane);
        __stcs(dst + r * 32 + lane, v);
        float w0 = ws[r], w1 = ws[128 + r], w2 = ws[256 + r], w3 = ws[384 + r];
        a0.x += w0 * v.x; a0.y += w0 * v.y; a0.z += w0 * v.z; a0.w += w0 * v.w;
        a1.x += w1 * v.x; a1.y += w1 * v.y; a1.z += w1 * v.z; a1.w += w1 * v.w;
        a2.x += w2 * v.x; a2.y += w2 * v.y; a2.z += w2 * v.z; a2.w += w2 * v.w;
        a3.x += w3 * v.x; a3.y += w3 * v.y; a3.z += w3 * v.z; a3.w += w3 * v.w;
    }
    float4* ap = (float4*)&accs[warp * 512];
    ap[lane] = a0; ap[32 + lane] = a1; ap[64 + lane] = a2; ap[96 + lane] = a3;
    __syncthreads();
    for (int idx = tid; idx < 512; idx += 256) {
        float s = 0.f;
#pragma unroll
        for (int w = 0; w < 8; w++) s += accs[w * 512 + idx];
        g_opart[((size_t)bg * 64 + chunk) * 512 + idx] = s;
    }
}

// K6: reduce chunk partials + add new-token contribution -> g_o[b][h][v]
__global__ void k_oreduce() {
    int bg = blockIdx.x;
    int b = bg >> 3, g = bg & 7;
    int idx = threadIdx.x; // 512
    int ri = idx >> 7, v = idx & 127;
    float s = 0.f;
    size_t base = (size_t)bg * 64 * 512 + idx;
    for (int c = 0; c < 64; c++) s += g_opart[base + c * 512];
    int h = ri * 8 + g;
    float wn = g_logits[(size_t)(b * 32 + h) * NM1 + 8192];
    float vn = g_proj[(b * 48 + 40 + g) * 128 + v];
    g_o[(b * 32 + h) * 128 + v] = s + wn * vn;
}

// K7: y partials: y[b,d] = sum_hv o[b,hv] * Wo[hv,d], split over hv. grid (32, 8)
__global__ void k_y_partial(const float* __restrict__ Wo) {
    int d0 = blockIdx.x * 128;
    int c = blockIdx.y;
    int hv0 = c * 512;
    int tid = threadIdx.x;
    __shared__ float os[16 * 512];
    for (int idx = tid; idx < 8192; idx += 128) {
        int b = idx >> 9, j = idx & 511;
        os[idx] = g_o[b * 4096 + hv0 + j];
    }
    __syncthreads();
    float acc[16];
#pragma unroll
    for (int b = 0; b < 16; b++) acc[b] = 0.f;
    for (int j = 0; j < 512; j += 4) {
        float w0 = Wo[(size_t)(hv0 + j + 0) * 4096 + d0 + tid];
        float w1 = Wo[(size_t)(hv0 + j + 1) * 4096 + d0 + tid];
        float w2 = Wo[(size_t)(hv0 + j + 2) * 4096 + d0 + tid];
        float w3 = Wo[(size_t)(hv0 + j + 3) * 4096 + d0 + tid];
#pragma unroll
        for (int b = 0; b < 16; b++) {
            float4 ov = *(const float4*)&os[b * 512 + j];
            acc[b] += ov.x * w0 + ov.y * w1 + ov.z * w2 + ov.w * w3;
        }
    }
#pragma unroll
    for (int b = 0; b < 16; b++)
        g_ypart[(c * 16 + b) * 4096 + d0 + tid] = acc[b];
}

// K8: reduce y partials into the output y region
__global__ void k_y_reduce(float* __restrict__ out) {
    int idx = blockIdx.x * blockDim.x + threadIdx.x; // 0..65535
    float s = 0.f;
#pragma unroll
    for (int c = 0; c < 8; c++) s += g_ypart[c * 65536 + idx];
    out[idx] = s;
}

extern "C" void kernel_launch(void* const* d_in, const int* in_sizes, int n_in,
                              void* d_out, int out_size) {
    const float* x     = (const float*)d_in[0];
    const float* prevK = (const float*)d_in[1];
    const float* prevV = (const float*)d_in[2];
    const float* Wq    = (const float*)d_in[3];
    const float* Wk    = (const float*)d_in[4];
    const float* Wv    = (const float*)d_in[5];
    const float* Wo    = (const float*)d_in[6];
    float* out = (float*)d_out;

    k_proj_partial<<<dim3(48, 8), 128>>>(x, Wq, Wk, Wv);
    k_proj_reduce<<<16 * 48, 128>>>(out);
    k_logits_copyK<<<16 * 8 * 64, 256>>>(prevK, out);
    k_softmax<<<16 * 32, 256>>>();
    k_attnV_copyV<<<16 * 8 * 64, 256>>>(prevV, out);
    k_oreduce<<<16 * 8, 512>>>();
    k_y_partial<<<dim3(32, 8), 128>>>(Wo);
    k_y_reduce<<<64, 1024>>>(out);
}

// round 2
// speedup vs baseline: 1.1604x; 1.1604x over previous
#include <cuda_runtime.h>

// Problem constants
#define NB 16
#define NH 32
#define NG 8
#define ND 4096
#define DK 128
#define DV 128
#define NM 8192
#define NM1 8193

// Output layout: y [16,4096] | Kc [16,8,8193,128] | Vc [16,8,8193,128]
static const long long KC_OFF = 65536LL;
static const long long VC_OFF = 65536LL + 16LL * 8 * 8193 * 128; // 134299648

// Scratch (device globals — no allocations allowed)
__device__ float g_proj_part[16 * 16 * 48 * 128];  // split-D partials for q/k_new/v_new
__device__ float g_proj[16 * 48 * 128];            // n<32: q[h], 32..39: k_new[g], 40..47: v_new[g]
__device__ float g_part[128 * 64 * 512];           // per-(b,g,chunk) partial o (4 heads x 128 v)
__device__ float g_stats[128 * 64 * 8];            // per-(b,g,chunk,head) {m, s}
__device__ float g_o[16 * 32 * 128];               // attention output per head
__device__ float g_ypart[16 * 16 * 4096];          // split-hv partials of y

// ---------------------------------------------------------------------------
// K1: projections, split over D. grid (48, 16), block 128 (k-index).
// n<32 -> q head n; 32..39 -> k_new group n-32; 40..47 -> v_new group n-40.
// ---------------------------------------------------------------------------
__global__ void k_proj_partial(const float* __restrict__ x,
                               const float* __restrict__ Wq,
                               const float* __restrict__ Wk,
                               const float* __restrict__ Wv) {
    int n = blockIdx.x;
    int c = blockIdx.y;
    int tid = threadIdx.x;
    int d0 = c * 256;
    const float* W = (n < 32) ? (Wq + (size_t)n * ND * DK)
                   : (n < 40) ? (Wk + (size_t)(n - 32) * ND * DK)
                              : (Wv + (size_t)(n - 40) * ND * DK);
    __shared__ float xs[16 * 256];
    for (int idx = tid; idx < 16 * 256; idx += 128) {
        int b = idx >> 8, d = idx & 255;
        xs[idx] = x[b * ND + d0 + d];
    }
    __syncthreads();
    float acc[16];
#pragma unroll
    for (int b = 0; b < 16; b++) acc[b] = 0.f;
    for (int d = 0; d < 256; d += 4) {
        float w0 = W[(size_t)(d0 + d + 0) * DK + tid];
        float w1 = W[(size_t)(d0 + d + 1) * DK + tid];
        float w2 = W[(size_t)(d0 + d + 2) * DK + tid];
        float w3 = W[(size_t)(d0 + d + 3) * DK + tid];
#pragma unroll
        for (int b = 0; b < 16; b++) {
            float4 xv = *(const float4*)&xs[b * 256 + d];
            acc[b] += xv.x * w0 + xv.y * w1 + xv.z * w2 + xv.w * w3;
        }
    }
#pragma unroll
    for (int b = 0; b < 16; b++)
        g_proj_part[((c * 16 + b) * 48 + n) * 128 + tid] = acc[b];
}

// K2: reduce split-D partials; also append new-token rows into Kc / Vc (m = 8192)
__global__ void k_proj_reduce(float* __restrict__ out) {
    int bn = blockIdx.x;
    int b = bn / 48, n = bn % 48;
    int tid = threadIdx.x;
    float s = 0.f;
#pragma unroll
    for (int c = 0; c < 16; c++)
        s += g_proj_part[((c * 16 + b) * 48 + n) * 128 + tid];
    g_proj[(b * 48 + n) * 128 + tid] = s;
    if (n >= 32 && n < 40) {
        out[KC_OFF + ((long long)(b * 8 + n - 32) * NM1 + NM) * 128 + tid] = s;
    } else if (n >= 40) {
        out[VC_OFF + ((long long)(b * 8 + n - 40) * NM1 + NM) * 128 + tid] = s;
    }
}

// ---------------------------------------------------------------------------
// K3 (fused): per (b,g,chunk of 128 rows):
//   A1: stream prev_K -> Kc, logits for 4 heads into smem
//   S : chunk-local softmax stats (m, s) + unnormalized weights e_i
//   A2: stream prev_V -> Vc, accumulate partial o = sum e_i * V_i
// Writes per-chunk (o_partial, m, s). grid = 128*64, block 256.
// ---------------------------------------------------------------------------
__global__ void k_fused_attn(const float* __restrict__ prevK,
                             const float* __restrict__ prevV,
                             float* __restrict__ out) {
    int bg = blockIdx.x >> 6;
    int chunk = blockIdx.x & 63;
    int b = bg >> 3, g = bg & 7;
    int tid = threadIdx.x, warp = tid >> 5, lane = tid & 31;
    int m0 = chunk * 128;

    __shared__ __align__(16) float qs[512];   // q for heads ri*8+g
    __shared__ __align__(16) float ls[512];   // logits -> weights [ri*128 + r]
    __shared__ float sstats[8];               // {m,s} per head
    __shared__ __align__(16) float accs[8 * 512];

    for (int idx = tid; idx < 512; idx += 256) {
        int ri = idx >> 7, k = idx & 127;
        qs[idx] = g_proj[(b * 48 + ri * 8 + g) * 128 + k];
    }
    __syncthreads();
    const float4* qs4 = (const float4*)qs;
    float4 q0 = qs4[lane], q1 = qs4[32 + lane], q2 = qs4[64 + lane], q3 = qs4[96 + lane];

    // ---- A1: K stream + logits ----
    const float4* srcK = (const float4*)(prevK + ((size_t)bg * NM + m0) * 128);
    float4* dstK = (float4*)(out + KC_OFF + ((long long)bg * NM1 + m0) * 128);
#pragma unroll 4
    for (int r = warp; r < 128; r += 8) {
        float4 kv = __ldcs(srcK + r * 32 + lane);
        __stcs(dstK + r * 32 + lane, kv);
        float s0 = kv.x * q0.x + kv.y * q0.y + kv.z * q0.z + kv.w * q0.w;
        float s1 = kv.x * q1.x + kv.y * q1.y + kv.z * q1.z + kv.w * q1.w;
        float s2 = kv.x * q2.x + kv.y * q2.y + kv.z * q2.z + kv.w * q2.w;
        float s3 = kv.x * q3.x + kv.y * q3.y + kv.z * q3.z + kv.w * q3.w;
#pragma unroll
        for (int off = 16; off > 0; off >>= 1) {
            s0 += __shfl_xor_sync(0xffffffffu, s0, off);
            s1 += __shfl_xor_sync(0xffffffffu, s1, off);
            s2 += __shfl_xor_sync(0xffffffffu, s2, off);
            s3 += __shfl_xor_sync(0xffffffffu, s3, off);
        }
        if (lane == 0) {
            ls[r] = s0; ls[128 + r] = s1; ls[256 + r] = s2; ls[384 + r] = s3;
        }
    }
    __syncthreads();

    // ---- S: chunk-local softmax stats; warp ri handles head ri ----
    if (warp < 4) {
        float4* lp = (float4*)(ls + warp * 128);
        float4 l = lp[lane];
        float m = fmaxf(fmaxf(l.x, l.y), fmaxf(l.z, l.w));
#pragma unroll
        for (int off = 16; off > 0; off >>= 1)
            m = fmaxf(m, __shfl_xor_sync(0xffffffffu, m, off));
        float4 e;
        e.x = __expf(l.x - m); e.y = __expf(l.y - m);
        e.z = __expf(l.z - m); e.w = __expf(l.w - m);
        float s = e.x + e.y + e.z + e.w;
#pragma unroll
        for (int off = 16; off > 0; off >>= 1)
            s += __shfl_xor_sync(0xffffffffu, s, off);
        lp[lane] = e;
        if (lane == 0) { sstats[warp * 2] = m; sstats[warp * 2 + 1] = s; }
    }
    __syncthreads();

    // ---- A2: V stream + weighted accumulation ----
    const float4* srcV = (const float4*)(prevV + ((size_t)bg * NM + m0) * 128);
    float4* dstV = (float4*)(out + VC_OFF + ((long long)bg * NM1 + m0) * 128);
    float4 a0 = {0, 0, 0, 0}, a1 = a0, a2 = a0, a3 = a0;
#pragma unroll 4
    for (int r = warp; r < 128; r += 8) {
        float4 v = __ldcs(srcV + r * 32 + lane);
        __stcs(dstV + r * 32 + lane, v);
        float w0 = ls[r], w1 = ls[128 + r], w2 = ls[256 + r], w3 = ls[384 + r];
        a0.x += w0 * v.x; a0.y += w0 * v.y; a0.z += w0 * v.z; a0.w += w0 * v.w;
        a1.x += w1 * v.x; a1.y += w1 * v.y; a1.z += w1 * v.z; a1.w += w1 * v.w;
        a2.x += w2 * v.x; a2.y += w2 * v.y; a2.z += w2 * v.z; a2.w += w2 * v.w;
        a3.x += w3 * v.x; a3.y += w3 * v.y; a3.z += w3 * v.z; a3.w += w3 * v.w;
    }
    float4* ap = (float4*)&accs[warp * 512];
    ap[lane] = a0; ap[32 + lane] = a1; ap[64 + lane] = a2; ap[96 + lane] = a3;
    __syncthreads();
    size_t pbase = ((size_t)bg * 64 + chunk) * 512;
    for (int idx = tid; idx < 512; idx += 256) {
        float s = 0.f;
#pragma unroll
        for (int w = 0; w < 8; w++) s += accs[w * 512 + idx];
        g_part[pbase + idx] = s;
    }
    if (tid < 8) g_stats[((size_t)bg * 64 + chunk) * 8 + tid] = sstats[tid];
}

// ---------------------------------------------------------------------------
// K4 (combine): per (b,h), merge 64 chunk partials + new-token term -> g_o.
// grid 512, block 128 (v-dim).
// ---------------------------------------------------------------------------
__global__ void k_combine() {
    int bh = blockIdx.x;
    int b = bh >> 5, h = bh & 31, g = h & 7, ri = h >> 3;
    int bg = b * 8 + g;
    int tid = threadIdx.x, warp = tid >> 5, lane = tid & 31;

    __shared__ float sm_m[64], sm_s[64], em[64];
    __shared__ float wsum[4];
    __shared__ float sM, sNewl;

    // new-token logit q . k_new
    float p = g_proj[(b * 48 + h) * 128 + tid] * g_proj[(b * 48 + 32 + g) * 128 + tid];
#pragma unroll
    for (int off = 16; off > 0; off >>= 1)
        p += __shfl_xor_sync(0xffffffffu, p, off);
    if (lane == 0) wsum[warp] = p;

    if (tid < 64) {
        sm_m[tid] = g_stats[((size_t)bg * 64 + tid) * 8 + ri * 2];
        sm_s[tid] = g_stats[((size_t)bg * 64 + tid) * 8 + ri * 2 + 1];
    }
    __syncthreads();
    if (tid == 0) {
        float newl = wsum[0] + wsum[1] + wsum[2] + wsum[3];
        float M = newl;
        for (int c = 0; c < 64; c++) M = fmaxf(M, sm_m[c]);
        sM = M; sNewl = newl;
    }
    __syncthreads();
    float M = sM;
    if (tid < 64) em[tid] = __expf(sm_m[tid] - M);
    __syncthreads();

    float enew = __expf(sNewl - M);
    float denom = enew;
    for (int c = 0; c < 64; c++) denom += sm_s[c] * em[c];

    float acc = enew * g_proj[(b * 48 + 40 + g) * 128 + tid];
    size_t base = (size_t)bg * 64 * 512 + ri * 128 + tid;
    for (int c = 0; c < 64; c++)
        acc += g_part[base + (size_t)c * 512] * em[c];
    g_o[(b * 32 + h) * 128 + tid] = acc / denom;
}

// K5: y partials: y[b,d] = sum_hv o[b,hv] * Wo[hv,d], split over hv. grid (32, 16)
__global__ void k_y_partial(const float* __restrict__ Wo) {
    int d0 = blockIdx.x * 128;
    int c = blockIdx.y;
    int hv0 = c * 256;
    int tid = threadIdx.x;
    __shared__ float os[16 * 256];
    for (int idx = tid; idx < 4096; idx += 128) {
        int b = idx >> 8, j = idx & 255;
        os[idx] = g_o[b * 4096 + hv0 + j];
    }
    __syncthreads();
    float acc[16];
#pragma unroll
    for (int b = 0; b < 16; b++) acc[b] = 0.f;
    for (int j = 0; j < 256; j += 4) {
        float w0 = Wo[(size_t)(hv0 + j + 0) * 4096 + d0 + tid];
        float w1 = Wo[(size_t)(hv0 + j + 1) * 4096 + d0 + tid];
        float w2 = Wo[(size_t)(hv0 + j + 2) * 4096 + d0 + tid];
        float w3 = Wo[(size_t)(hv0 + j + 3) * 4096 + d0 + tid];
#pragma unroll
        for (int b = 0; b < 16; b++) {
            float4 ov = *(const float4*)&os[b * 256 + j];
            acc[b] += ov.x * w0 + ov.y * w1 + ov.z * w2 + ov.w * w3;
        }
    }
#pragma unroll
    for (int b = 0; b < 16; b++)
        g_ypart[(c * 16 + b) * 4096 + d0 + tid] = acc[b];
}

// K6: reduce y partials into the output y region
__global__ void k_y_reduce(float* __restrict__ out) {
    int idx = blockIdx.x * blockDim.x + threadIdx.x; // 0..65535
    float s = 0.f;
#pragma unroll
    for (int c = 0; c < 16; c++) s += g_ypart[c * 65536 + idx];
    out[idx] = s;
}

extern "C" void kernel_launch(void* const* d_in, const int* in_sizes, int n_in,
                              void* d_out, int out_size) {
    const float* x     = (const float*)d_in[0];
    const float* prevK = (const float*)d_in[1];
    const float* prevV = (const float*)d_in[2];
    const float* Wq    = (const float*)d_in[3];
    const float* Wk    = (const float*)d_in[4];
    const float* Wv    = (const float*)d_in[5];
    const float* Wo    = (const float*)d_in[6];
    float* out = (float*)d_out;

    k_proj_partial<<<dim3(48, 16), 128>>>(x, Wq, Wk, Wv);
    k_proj_reduce<<<16 * 48, 128>>>(out);
    k_fused_attn<<<128 * 64, 256>>>(prevK, prevV, out);
    k_combine<<<16 * 32, 128>>>();
    k_y_partial<<<dim3(32, 16), 128>>>(Wo);
    k_y_reduce<<<64, 1024>>>(out);
}